// round 17
// baseline (speedup 1.0000x reference)
#include <cuda_runtime.h>
#include <cuda.h>
#include <cuda_fp16.h>
#include <cstdint>
#include <cstddef>

#define HID    1024
#define INTER_ 2816
#define MAX_T  8192
#define NEXP   8
#define HI     ((size_t)HID * INTER_)
#define NT_F   (INTER_ / 128)     // 22 fused n-tiles

// ---------------------------------------------------------------------------
// Scratch (static device globals; allocation-free rule)
// ---------------------------------------------------------------------------
__device__ __align__(128) __half g_xh[(size_t)MAX_T * HID];          // x fp16 [T][H]
__device__ __align__(128) __half g_wg[(size_t)NEXP * HID * INTER_];  // gate fp16 [E][H][I]
__device__ __align__(128) __half g_wu[(size_t)NEXP * HID * INTER_];  // up fp16   [E][H][I]
__device__ __align__(128) __half g_wd[(size_t)NEXP * HID * INTER_];  // down fp16 [E][I][H]
__device__ __align__(128) __half g_inter[(size_t)MAX_T * INTER_];    // [T][I]
// [0]=cvt ticket  [1]=fused-row done count  [2+e]=fusedDone[e]  [10+e]=wdDone[e]
__device__ int g_flags[18];

// ---------------------------------------------------------------------------
// Helpers
// ---------------------------------------------------------------------------
__device__ __forceinline__ uint32_t smem_u32(const void* p) {
    uint32_t a;
    asm("{ .reg .u64 t; cvta.to.shared.u64 t, %1; cvt.u32.u64 %0, t; }" : "=r"(a) : "l"(p));
    return a;
}
__device__ __forceinline__ uint32_t f22u(float a, float b) {
    __half2 h = __floats2half2_rn(a, b);
    return *reinterpret_cast<uint32_t*>(&h);
}

#define CP_ASYNC(sm, gm) \
    asm volatile("cp.async.cg.shared.global [%0], [%1], 16;" :: "r"(sm), "l"(gm))
#define CP_COMMIT() asm volatile("cp.async.commit_group;" ::: "memory")
#define CP_WAIT2()  asm volatile("cp.async.wait_group 2;" ::: "memory")

__device__ __forceinline__ void ldm_x4(uint32_t& r0, uint32_t& r1, uint32_t& r2,
                                       uint32_t& r3, uint32_t addr) {
    asm volatile("ldmatrix.sync.aligned.m8n8.x4.shared.b16 {%0,%1,%2,%3}, [%4];"
                 : "=r"(r0), "=r"(r1), "=r"(r2), "=r"(r3) : "r"(addr));
}
__device__ __forceinline__ void ldm_x4_trans(uint32_t& r0, uint32_t& r1, uint32_t& r2,
                                             uint32_t& r3, uint32_t addr) {
    asm volatile("ldmatrix.sync.aligned.m8n8.x4.trans.shared.b16 {%0,%1,%2,%3}, [%4];"
                 : "=r"(r0), "=r"(r1), "=r"(r2), "=r"(r3) : "r"(addr));
}
__device__ __forceinline__ void mma_f16(float* c, const uint32_t* a, const uint32_t* b) {
    asm volatile(
        "mma.sync.aligned.m16n8k16.row.col.f32.f16.f16.f32 "
        "{%0,%1,%2,%3}, {%4,%5,%6,%7}, {%8,%9}, {%0,%1,%2,%3};"
        : "+f"(c[0]), "+f"(c[1]), "+f"(c[2]), "+f"(c[3])
        : "r"(a[0]), "r"(a[1]), "r"(a[2]), "r"(a[3]), "r"(b[0]), "r"(b[1]));
}

// ---------------------------------------------------------------------------
// Pre-pass: fp32 -> fp16 RN for x, gate, up; zeroes flags.
// ---------------------------------------------------------------------------
__global__ void cvt_xgu_kernel(const float* __restrict__ x,
                               const float* __restrict__ gate,
                               const float* __restrict__ up, int T)
{
    if (blockIdx.x == 0 && blockIdx.y == 0 && threadIdx.x < 18)
        g_flags[threadIdx.x] = 0;
    const float* src;
    __half* dst;
    size_t n8;
    switch (blockIdx.y) {
        case 0:  src = x;    dst = g_xh; n8 = (size_t)T * HID / 8; break;
        case 1:  src = gate; dst = g_wg; n8 = (size_t)NEXP * HI / 8; break;
        default: src = up;   dst = g_wu; n8 = (size_t)NEXP * HI / 8; break;
    }
    size_t i  = (size_t)blockIdx.x * blockDim.x + threadIdx.x;
    size_t st = (size_t)gridDim.x * blockDim.x;
    const float4* in = (const float4*)src;
    uint4* out = (uint4*)dst;
    for (; i < n8; i += st) {
        float4 a = in[2 * i], b = in[2 * i + 1];
        uint4 v;
        v.x = f22u(a.x, a.y); v.y = f22u(a.z, a.w);
        v.z = f22u(b.x, b.y); v.w = f22u(b.z, b.w);
        out[i] = v;
    }
}

// ---------------------------------------------------------------------------
// Tiling constants (halves).
// ---------------------------------------------------------------------------
#define BK        32
#define STAGES    4
#define ASTRIDE   40
#define BSTR_F    136
#define BSTR_D    264
#define TA_BYTES  (128 * ASTRIDE * 2)        // 10240
#define BF_BYTES  (BK * BSTR_F * 2)          // 8704
#define BD_BYTES  (BK * BSTR_D * 2)          // 16896
#define FS_STAGE  (TA_BYTES + 2 * BF_BYTES)  // 27648
#define DS_STAGE  (TA_BYTES + BD_BYTES)      // 27136
#define SMEM_MAX  (STAGES * FS_STAGE)        // 110592 (covers both paths)

// Down-weight convert queue: 32768-float chunks, expert-major (88 per expert).
#define CHUNK_FL  32768
#define CPM       88
#define NCHUNK    (NEXP * CPM)               // 704
#define NQ_TAIL   140

__device__ __forceinline__ void load_tileA(uint32_t sdst, const __half* g, size_t ld,
                                           int tid, int maxrow) {
    #pragma unroll
    for (int j = 0; j < 2; ++j) {
        int idx = tid + j * 256;
        int r = idx >> 2, c = idx & 3;
        int gr = (r < maxrow) ? r : 0;
        CP_ASYNC(sdst + (r * ASTRIDE + c * 8) * 2, g + (size_t)gr * ld + c * 8);
    }
}
__device__ __forceinline__ void load_tileBF(uint32_t sdst, const __half* g, size_t ld,
                                            int tid) {
    #pragma unroll
    for (int j = 0; j < 2; ++j) {
        int idx = tid + j * 256;
        int r = idx >> 4, c = idx & 15;
        CP_ASYNC(sdst + (r * BSTR_F + c * 8) * 2, g + (size_t)r * ld + c * 8);
    }
}
__device__ __forceinline__ void load_tileBD(uint32_t sdst, const __half* g, size_t ld,
                                            int tid) {
    #pragma unroll
    for (int j = 0; j < 4; ++j) {
        int idx = tid + j * 256;
        int r = idx >> 5, c = idx & 31;
        CP_ASYNC(sdst + (r * BSTR_D + c * 8) * 2, g + (size_t)r * ld + c * 8);
    }
}

// ---------------------------------------------------------------------------
// Exact tile cover: linear m-tile id -> (expert, start, cnt, m0).
// ---------------------------------------------------------------------------
__device__ __forceinline__ bool map_tile(const int* __restrict__ tpe, int t,
                                         int& e, int& start, int& cnt, int& m0) {
    int rem = t, st = 0;
    #pragma unroll
    for (int i = 0; i < NEXP; ++i) {
        const int c = __ldg(&tpe[i]);
        const int nt = (c + 127) >> 7;
        if (rem < nt) { e = i; start = st; cnt = c; m0 = rem << 7; return true; }
        rem -= nt;
        st += c;
    }
    return false;
}

// One CTA converts one 32768-float chunk (16 uint4 per thread).
__device__ __forceinline__ void cvt_chunk_cta(const float* __restrict__ down_raw,
                                              int c, int tid) {
    const float4* in = (const float4*)(down_raw + (size_t)c * CHUNK_FL);
    uint4* out = (uint4*)(g_wd + (size_t)c * CHUNK_FL);
    #pragma unroll 4
    for (int j = 0; j < 16; ++j) {
        const int idx = tid + j * 256;
        float4 a = in[2 * idx], b = in[2 * idx + 1];
        uint4 v;
        v.x = f22u(a.x, a.y); v.y = f22u(a.z, a.w);
        v.z = f22u(b.x, b.y); v.w = f22u(b.z, b.w);
        out[idx] = v;
    }
}

// ---------------------------------------------------------------------------
// Fused gate/up compute stage
// ---------------------------------------------------------------------------
__device__ __forceinline__ void compute_stage_fused(
    uint32_t sbase, uint32_t aOff, uint32_t bOff,
    float cg[4][4][4], float cu[4][4][4])
{
    const uint32_t aA = sbase + aOff;
    const uint32_t aG = sbase + TA_BYTES + bOff;
    const uint32_t aU = aG + BF_BYTES;
    #pragma unroll
    for (int ks = 0; ks < 2; ++ks) {
        uint32_t a[4][4];
        #pragma unroll
        for (int mt = 0; mt < 4; ++mt)
            ldm_x4(a[mt][0], a[mt][1], a[mt][2], a[mt][3], aA + ks * 32 + mt * 1280);
        uint32_t bg[4][2], bu[4][2];
        const uint32_t ksb = ks * 16 * BSTR_F * 2;
        #pragma unroll
        for (int p = 0; p < 2; ++p) {
            ldm_x4_trans(bg[2*p][0], bg[2*p][1], bg[2*p+1][0], bg[2*p+1][1],
                         aG + ksb + p * 32);
            ldm_x4_trans(bu[2*p][0], bu[2*p][1], bu[2*p+1][0], bu[2*p+1][1],
                         aU + ksb + p * 32);
        }
        #pragma unroll
        for (int mt = 0; mt < 4; ++mt)
            #pragma unroll
            for (int nt = 0; nt < 4; ++nt) {
                mma_f16(cg[mt][nt], a[mt], bg[nt]);
                mma_f16(cu[mt][nt], a[mt], bu[nt]);
            }
    }
}

__device__ __forceinline__ void compute_stage_down(
    uint32_t sbase, uint32_t aOff, uint32_t bOff, float cc[4][8][4])
{
    const uint32_t aA = sbase + aOff;
    const uint32_t aB = sbase + TA_BYTES + bOff;
    #pragma unroll
    for (int ks = 0; ks < 2; ++ks) {
        uint32_t a[4][4];
        #pragma unroll
        for (int mt = 0; mt < 4; ++mt)
            ldm_x4(a[mt][0], a[mt][1], a[mt][2], a[mt][3], aA + ks * 32 + mt * 1280);
        uint32_t bf[8][2];
        const uint32_t ksb = ks * 16 * BSTR_D * 2;
        #pragma unroll
        for (int p = 0; p < 4; ++p)
            ldm_x4_trans(bf[2*p][0], bf[2*p][1], bf[2*p+1][0], bf[2*p+1][1],
                         aB + ksb + p * 32);
        #pragma unroll
        for (int mt = 0; mt < 4; ++mt)
            #pragma unroll
            for (int nt = 0; nt < 8; ++nt)
                mma_f16(cc[mt][nt], a[mt], bf[nt]);
    }
}

// ---------------------------------------------------------------------------
// Merged MoE kernel.
//   y in [0, tcover)          : fused gate/up GEMM + SwiGLU  (+ tail converts)
//   y in [tcover, tcover+DR)  : down-proj tiles, gated on fusedDone[e] &&
//                               wdDone[e]; convert wd chunks while waiting.
// Down bids come after ALL fused bids, so no fused CTA can queue behind a
// waiting down CTA (deadlock-free by dispatch order).
// ---------------------------------------------------------------------------
__global__ __launch_bounds__(256, 1)
void moe_mlp(const __half* __restrict__ X, const __half* __restrict__ WG,
             const __half* __restrict__ WU, __half* __restrict__ INTER,
             float* __restrict__ OUT, const int* __restrict__ tpe,
             const float* __restrict__ down_raw, int tcover)
{
    const int tid = threadIdx.x;
    extern __shared__ __half sm[];
    const uint32_t sb = smem_u32(sm);
    __shared__ int s_tok;

    if ((int)blockIdx.y < tcover) {
        // ================= fused gate/up path =================
        int e, start, cnt, m0;
        const bool valid = map_tile(tpe, blockIdx.y, e, start, cnt, m0);

        if (valid) {
            const int rows = min(128, cnt - m0);
            const int n0 = blockIdx.x * 128;
            const int wid = tid >> 5, lane = tid & 31;
            const int wm = wid & 1, wn = wid >> 1;

            const __half* Ag = X  + (size_t)(start + m0) * HID;
            const __half* Gg = WG + (size_t)e * HI + n0;
            const __half* Ug = WU + (size_t)e * HI + n0;

            const uint32_t aOff = ((wm * 64 + (lane & 15)) * ASTRIDE + (lane >> 4) * 8) * 2;
            const uint32_t bRow = ((lane >> 3) & 1) * 8 + (lane & 7);
            const uint32_t bOff = (bRow * BSTR_F + wn * 32 + (lane >> 4) * 8) * 2;

            float cg[4][4][4], cu[4][4][4];
            #pragma unroll
            for (int a = 0; a < 4; ++a)
                #pragma unroll
                for (int b = 0; b < 4; ++b)
                    #pragma unroll
                    for (int c = 0; c < 4; ++c) { cg[a][b][c] = 0.f; cu[a][b][c] = 0.f; }

            const int niter = HID / BK;  // 32
            #pragma unroll
            for (int s = 0; s < STAGES - 1; ++s) {
                const uint32_t st = sb + s * FS_STAGE;
                load_tileA (st,                       Ag + s * BK, HID, tid, rows);
                load_tileBF(st + TA_BYTES,            Gg + (size_t)s * BK * INTER_, INTER_, tid);
                load_tileBF(st + TA_BYTES + BF_BYTES, Ug + (size_t)s * BK * INTER_, INTER_, tid);
                CP_COMMIT();
            }
            for (int i = 0; i < niter; ++i) {
                CP_WAIT2();
                __syncthreads();
                compute_stage_fused(sb + (i % STAGES) * FS_STAGE, aOff, bOff, cg, cu);
                const int nb = i + STAGES - 1;
                if (nb < niter) {
                    const uint32_t st = sb + (nb % STAGES) * FS_STAGE;
                    load_tileA (st,                       Ag + nb * BK, HID, tid, rows);
                    load_tileBF(st + TA_BYTES,            Gg + (size_t)nb * BK * INTER_, INTER_, tid);
                    load_tileBF(st + TA_BYTES + BF_BYTES, Ug + (size_t)nb * BK * INTER_, INTER_, tid);
                }
                CP_COMMIT();
            }

            const int rbase = wm * 64 + (lane >> 2);
            const int cbase = n0 + wn * 32 + 2 * (lane & 3);
            #pragma unroll
            for (int mt = 0; mt < 4; ++mt) {
                #pragma unroll
                for (int nt = 0; nt < 4; ++nt) {
                    const int r0 = rbase + mt * 16;
                    const int c  = cbase + nt * 8;
                    if (r0 < rows) {
                        float a0 = cg[mt][nt][0], a1 = cg[mt][nt][1];
                        uint32_t v = f22u(a0 / (1.f + __expf(-a0)) * cu[mt][nt][0],
                                          a1 / (1.f + __expf(-a1)) * cu[mt][nt][1]);
                        *(uint32_t*)(INTER + (size_t)(start + m0 + r0) * INTER_ + c) = v;
                    }
                    if (r0 + 8 < rows) {
                        float a2 = cg[mt][nt][2], a3 = cg[mt][nt][3];
                        uint32_t v = f22u(a2 / (1.f + __expf(-a2)) * cu[mt][nt][2],
                                          a3 / (1.f + __expf(-a3)) * cu[mt][nt][3]);
                        *(uint32_t*)(INTER + (size_t)(start + m0 + r0 + 8) * INTER_ + c) = v;
                    }
                }
            }
            __syncthreads();
            if (tid == 0) { __threadfence(); atomicAdd(&g_flags[2 + e], 1); }
        }

        // Tail-gated wd conversion (R16): only when < NQ_TAIL fused CTAs remain.
        const int ftotal = (int)gridDim.x * tcover;
        if (tid == 0) s_tok = atomicAdd(&g_flags[1], 1);
        __syncthreads();
        if (s_tok < ftotal - NQ_TAIL) return;

        for (;;) {
            if (tid == 0) s_tok = atomicAdd(&g_flags[0], 1);
            __syncthreads();
            const int c = s_tok;
            __syncthreads();
            if (c >= NCHUNK) return;
            cvt_chunk_cta(down_raw, c, tid);
            if (tid == 0) { __threadfence(); atomicAdd(&g_flags[10 + c / CPM], 1); }
        }
    }

    // ================= down-proj path =================
    const int t = ((int)blockIdx.y - tcover) * NT_F + (int)blockIdx.x;
    int e, start, cnt, m0;
    const bool valid = map_tile(tpe, t >> 2, e, start, cnt, m0);

    if (!valid) {
        // padding: free converter, then exit
        for (;;) {
            if (tid == 0) s_tok = atomicAdd(&g_flags[0], 1);
            __syncthreads();
            const int c = s_tok;
            __syncthreads();
            if (c >= NCHUNK) return;
            cvt_chunk_cta(down_raw, c, tid);
            if (tid == 0) { __threadfence(); atomicAdd(&g_flags[10 + c / CPM], 1); }
        }
    }

    const int ftarget = NT_F * ((cnt + 127) >> 7);
    __shared__ int s_state;
    for (;;) {
        if (tid == 0) {
            volatile int* fl = g_flags;
            s_state = (fl[2 + e] >= ftarget && fl[10 + e] >= CPM) ? 1 : 0;
        }
        __syncthreads();
        if (s_state) break;
        // convert while waiting (this CTA owns a whole SM; spinning wastes it)
        if (tid == 0) s_tok = atomicAdd(&g_flags[0], 1);
        __syncthreads();
        const int c = s_tok;
        __syncthreads();
        if (c < NCHUNK) {
            cvt_chunk_cta(down_raw, c, tid);
            if (tid == 0) { __threadfence(); atomicAdd(&g_flags[10 + c / CPM], 1); }
        } else {
            if (tid == 0) __nanosleep(256);
        }
        __syncthreads();
    }
    asm volatile("membar.gl;" ::: "memory");

    {
        const int rows = min(128, cnt - m0);
        const int n0 = (t & 3) * 256;
        const int wid = tid >> 5, lane = tid & 31;
        const int wm = wid & 1, wn = wid >> 1;

        const __half* Ag = INTER + (size_t)(start + m0) * INTER_;
        const __half* Bg = g_wd + (size_t)e * HI + n0;

        const uint32_t aOff = ((wm * 64 + (lane & 15)) * ASTRIDE + (lane >> 4) * 8) * 2;
        const uint32_t bRow = ((lane >> 3) & 1) * 8 + (lane & 7);
        const uint32_t bOff = (bRow * BSTR_D + wn * 64 + (lane >> 4) * 8) * 2;

        float cc[4][8][4];
        #pragma unroll
        for (int a = 0; a < 4; ++a)
            #pragma unroll
            for (int b = 0; b < 8; ++b)
                #pragma unroll
                for (int c = 0; c < 4; ++c) cc[a][b][c] = 0.f;

        const int niter = INTER_ / BK;  // 88
        #pragma unroll
        for (int s = 0; s < STAGES - 1; ++s) {
            const uint32_t st = sb + s * DS_STAGE;
            load_tileA (st,            Ag + s * BK, INTER_, tid, rows);
            load_tileBD(st + TA_BYTES, Bg + (size_t)s * BK * HID, HID, tid);
            CP_COMMIT();
        }
        for (int i = 0; i < niter; ++i) {
            CP_WAIT2();
            __syncthreads();
            compute_stage_down(sb + (i % STAGES) * DS_STAGE, aOff, bOff, cc);
            const int nb = i + STAGES - 1;
            if (nb < niter) {
                const uint32_t st = sb + (nb % STAGES) * DS_STAGE;
                load_tileA (st,            Ag + nb * BK, INTER_, tid, rows);
                load_tileBD(st + TA_BYTES, Bg + (size_t)nb * BK * HID, HID, tid);
            }
            CP_COMMIT();
        }

        const int rbase = wm * 64 + (lane >> 2);
        const int cbase = n0 + wn * 64 + 2 * (lane & 3);
        #pragma unroll
        for (int mt = 0; mt < 4; ++mt) {
            #pragma unroll
            for (int nt = 0; nt < 8; ++nt) {
                const int r0 = rbase + mt * 16;
                const int c  = cbase + nt * 8;
                if (r0 < rows) {
                    float2 v = make_float2(cc[mt][nt][0], cc[mt][nt][1]);
                    *reinterpret_cast<float2*>(OUT + (size_t)(start + m0 + r0) * HID + c) = v;
                }
                if (r0 + 8 < rows) {
                    float2 v = make_float2(cc[mt][nt][2], cc[mt][nt][3]);
                    *reinterpret_cast<float2*>(OUT + (size_t)(start + m0 + r0 + 8) * HID + c) = v;
                }
            }
        }
    }
}

// ---------------------------------------------------------------------------
// Host side: single stream, two plain launches.
// ---------------------------------------------------------------------------
extern "C" void kernel_launch(void* const* d_in, const int* in_sizes, int n_in,
                              void* d_out, int out_size)
{
    const float* x    = (const float*)d_in[0];   // [T, H]
    const float* gate = (const float*)d_in[1];   // [E, H, I]
    const float* up   = (const float*)d_in[2];   // [E, H, I]
    const float* down = (const float*)d_in[3];   // [E, I, H]
    const int*   tpe  = (const int*)d_in[4];     // [E]
    float* out = (float*)d_out;                  // [T, H]

    const int T = in_sizes[0] / HID;

    __half *xh, *wg, *wu, *inter;
    cudaGetSymbolAddress((void**)&xh, g_xh);
    cudaGetSymbolAddress((void**)&wg, g_wg);
    cudaGetSymbolAddress((void**)&wu, g_wu);
    cudaGetSymbolAddress((void**)&inter, g_inter);

    cudaFuncSetAttribute(moe_mlp, cudaFuncAttributeMaxDynamicSharedMemorySize, SMEM_MAX);

    // 1) Pre-pass: convert x, gate, up; zero flags.
    cvt_xgu_kernel<<<dim3(4096, 3), 256>>>(x, gate, up, T);

    // 2) Merged fused-GEMM + down-proj kernel.
    const int tcover = (T + 127) / 128 + NEXP;
    const int drows  = (4 * tcover + NT_F - 1) / NT_F;   // down tiles as y-rows
    dim3 g(NT_F, tcover + drows);
    moe_mlp<<<g, 256, SMEM_MAX>>>(xh, wg, wu, inter, out, tpe, down, tcover);
}